// round 1
// baseline (speedup 1.0000x reference)
#include <cuda_runtime.h>

#define D    64
#define NN   72          // nodes per graph
#define E    288         // edges per graph
#define NM   (NN*NN)     // 5184 (output is NM x NM)

// ---- scratch (no allocations allowed) ----
__device__ float g_A1[NN * D];   // F2 @ relu(l1)^T
__device__ float g_A2[NN * D];   // F2 @ relu(l2)^T
__device__ float g_G1[E * D];    // per-G1-edge endpoint feature sum
__device__ float g_P [E * D];    // per-G2-edge projected sum

// ---------------------------------------------------------------------------
// 1) zero the 107.5 MB output with vectorized stores (dominant cost)
// ---------------------------------------------------------------------------
__global__ void zero_kernel(float4* __restrict__ out, int n4) {
    int i = blockIdx.x * blockDim.x + threadIdx.x;
    if (i < n4) out[i] = make_float4(0.f, 0.f, 0.f, 0.f);
}

// ---------------------------------------------------------------------------
// 2) A1[n,r] = sum_c relu(l1[r,c]) * F2[n,c];  A2 likewise with l2
// ---------------------------------------------------------------------------
__global__ void a_kernel(const float* __restrict__ F2,
                         const float* __restrict__ l1,
                         const float* __restrict__ l2) {
    __shared__ float f[D];
    int n = blockIdx.x;       // node
    int r = threadIdx.x;      // output feature
    f[r] = F2[n * D + r];
    __syncthreads();
    float s1 = 0.f, s2 = 0.f;
    #pragma unroll
    for (int c = 0; c < D; c++) {
        float v = f[c];
        s1 = fmaf(fmaxf(l1[r * D + c], 0.f), v, s1);
        s2 = fmaf(fmaxf(l2[r * D + c], 0.f), v, s2);
    }
    g_A1[n * D + r] = s1;
    g_A2[n * D + r] = s2;
}

// ---------------------------------------------------------------------------
// 3) G1[e] = F1[src1[e]] + F1[dst1[e]];  P[e] = A1[src2[e]] + A2[dst2[e]]
// ---------------------------------------------------------------------------
__global__ void gather_kernel(const float* __restrict__ F1,
                              const int* __restrict__ s1, const int* __restrict__ d1,
                              const int* __restrict__ s2, const int* __restrict__ d2) {
    int e = blockIdx.x;
    int r = threadIdx.x;
    g_G1[e * D + r] = F1[s1[e] * D + r] + F1[d1[e] * D + r];
    g_P [e * D + r] = g_A1[s2[e] * D + r] + g_A2[d2[e] * D + r];
}

// ---------------------------------------------------------------------------
// 4) diagonal: out[k,k] = U1[k/72] . U2[k%72]   (plain store; runs before scatter)
// ---------------------------------------------------------------------------
__global__ void diag_kernel(const float* __restrict__ U1,
                            const float* __restrict__ U2,
                            float* __restrict__ out) {
    int k = blockIdx.x * blockDim.x + threadIdx.x;
    if (k >= NM) return;
    int a = k / NN, b = k % NN;
    const float* u1 = U1 + a * D;
    const float* u2 = U2 + b * D;
    float s = 0.f;
    #pragma unroll
    for (int c = 0; c < D; c++) s = fmaf(u1[c], u2[c], s);
    out[(size_t)k * NM + k] = s;
}

// ---------------------------------------------------------------------------
// 5) scatter: for each edge pair (j in G2, i in G1):
//      w = G1[j] . P[i]
//      add w to out[(a*72+b), (c*72+d)] for a,c in {src2[j],dst2[j]},
//                                           b,d in {src1[i],dst1[i]}  (16 cells)
//    16x16 edge-pair tiles; tile features staged in smem (65-pad: no conflicts)
// ---------------------------------------------------------------------------
__global__ void scatter_kernel(const int* __restrict__ s1, const int* __restrict__ d1,
                               const int* __restrict__ s2, const int* __restrict__ d2,
                               float* __restrict__ out) {
    __shared__ float Gj[16][65];
    __shared__ float Pi[16][65];
    __shared__ int ea1[16], ea2[16], eb1[16], eb2[16];

    int jb = blockIdx.y * 16;   // G2-edge tile base
    int ib = blockIdx.x * 16;   // G1-edge tile base
    int t  = threadIdx.x;       // 256 threads

    for (int q = t; q < 16 * D; q += 256) {
        int row = q >> 6, c = q & 63;
        Gj[row][c] = g_G1[(jb + row) * D + c];
        Pi[row][c] = g_P [(ib + row) * D + c];
    }
    if (t < 16)            { ea1[t] = s2[jb + t];       ea2[t] = d2[jb + t]; }
    else if (t < 32)       { int u = t - 16; eb1[u] = s1[ib + u]; eb2[u] = d1[ib + u]; }
    __syncthreads();

    int jj = t >> 4, ii = t & 15;
    float w = 0.f;
    #pragma unroll
    for (int c = 0; c < D; c++) w = fmaf(Gj[jj][c], Pi[ii][c], w);

    int a1 = ea1[jj], a2 = ea2[jj], b1 = eb1[ii], b2 = eb2[ii];
    int rr[4];
    rr[0] = a1 * NN + b1;
    rr[1] = a1 * NN + b2;
    rr[2] = a2 * NN + b1;
    rr[3] = a2 * NN + b2;
    #pragma unroll
    for (int x = 0; x < 4; x++) {
        float* rowp = out + (size_t)rr[x] * NM;
        #pragma unroll
        for (int y = 0; y < 4; y++)
            atomicAdd(rowp + rr[y], w);
    }
}

// ---------------------------------------------------------------------------
extern "C" void kernel_launch(void* const* d_in, const int* in_sizes, int n_in,
                              void* d_out, int out_size) {
    const float* F1 = (const float*)d_in[0];
    const float* F2 = (const float*)d_in[1];
    const float* U1 = (const float*)d_in[2];
    const float* U2 = (const float*)d_in[3];
    const float* l1 = (const float*)d_in[4];
    const float* l2 = (const float*)d_in[5];
    const int*   s1 = (const int*)d_in[6];
    const int*   dd1 = (const int*)d_in[7];
    const int*   s2 = (const int*)d_in[8];
    const int*   dd2 = (const int*)d_in[9];
    float* out = (float*)d_out;

    const int n4 = (NM * NM) / 4;                     // 6,718,464 float4
    zero_kernel<<<(n4 + 255) / 256, 256>>>((float4*)out, n4);
    a_kernel<<<NN, D>>>(F2, l1, l2);
    gather_kernel<<<E, D>>>(F1, s1, dd1, s2, dd2);
    diag_kernel<<<(NM + 127) / 128, 128>>>(U1, U2, out);
    scatter_kernel<<<dim3(E / 16, E / 16), 256>>>(s1, dd1, s2, dd2, out);
}